// round 1
// baseline (speedup 1.0000x reference)
#include <cuda_runtime.h>

#define BATCH 8
#define NPTS  32768
#define DIM   256
#define SPTS  64
#define NS    8
#define R2    16.0f

// ---------------- scratch (no allocations allowed) ----------------
__device__ float g_sox[BATCH*NPTS];
__device__ float g_soy[BATCH*NPTS];
__device__ float g_soz[BATCH*NPTS];
__device__ int   g_fps[BATCH*SPTS];
__device__ float g_scoor[BATCH*SPTS*3];
__device__ float g_dcoor[BATCH*SPTS*3];
__device__ float g_diffx[BATCH*SPTS*DIM];
__device__ float g_sampx[BATCH*SPTS*DIM];
__device__ float g_lnq[BATCH*SPTS*DIM];
__device__ float g_lnk[BATCH*SPTS*DIM];
__device__ float g_q[BATCH*SPTS*DIM];
__device__ float g_k[BATCH*SPTS*DIM];

// ---------------- K1: pack coor -> SoA ----------------
__global__ void pack_kernel(const float* __restrict__ coor) {
    int e = blockIdx.x * blockDim.x + threadIdx.x;   // 0 .. 262143
    float x = coor[3*e+0];
    float y = coor[3*e+1];
    float z = coor[3*e+2];
    g_sox[e] = x; g_soy[e] = y; g_soz[e] = z;
}

// ---------------- K2: farthest point sampling ----------------
// one CTA per batch, dists held in registers (64 per thread)
__global__ __launch_bounds__(512, 1) void fps_kernel() {
    const int b    = blockIdx.x;
    const int tid  = threadIdx.x;
    const int lane = tid & 31;
    const int wid  = tid >> 5;

    __shared__ float s_rv[16];
    __shared__ int   s_ri[16];
    __shared__ float s_c[3];
    __shared__ int   s_far;

    const float4* x4 = (const float4*)(g_sox + b * NPTS);
    const float4* y4 = (const float4*)(g_soy + b * NPTS);
    const float4* z4 = (const float4*)(g_soz + b * NPTS);

    float dist[64];
#pragma unroll
    for (int i = 0; i < 64; i++) dist[i] = 1e10f;

    if (tid == 0) {
        s_far  = 0;
        s_c[0] = g_sox[b * NPTS];
        s_c[1] = g_soy[b * NPTS];
        s_c[2] = g_soz[b * NPTS];
    }
    __syncthreads();

    for (int it = 0; it < SPTS; it++) {
        float cx = s_c[0], cy = s_c[1], cz = s_c[2];
        if (tid == 0) {
            g_fps[b * SPTS + it] = s_far;                 // emit incoming "far"
            g_scoor[(b * SPTS + it) * 3 + 0] = cx;
            g_scoor[(b * SPTS + it) * 3 + 1] = cy;
            g_scoor[(b * SPTS + it) * 3 + 2] = cz;
        }
        if (it == SPTS - 1) break;

        float bestv = -1.0f;
        int   besti = 0;
#pragma unroll
        for (int k = 0; k < 16; k++) {
            int c = k * 512 + tid;                // float4 chunk index
            float4 xx = x4[c], yy = y4[c], zz = z4[c];
            int pbase = c * 4;
            {
                float dx = xx.x - cx, dy = yy.x - cy, dz = zz.x - cz;
                float d2 = dx*dx + dy*dy + dz*dz;
                float nd = fminf(dist[4*k+0], d2); dist[4*k+0] = nd;
                if (nd > bestv) { bestv = nd; besti = pbase + 0; }
            }
            {
                float dx = xx.y - cx, dy = yy.y - cy, dz = zz.y - cz;
                float d2 = dx*dx + dy*dy + dz*dz;
                float nd = fminf(dist[4*k+1], d2); dist[4*k+1] = nd;
                if (nd > bestv) { bestv = nd; besti = pbase + 1; }
            }
            {
                float dx = xx.z - cx, dy = yy.z - cy, dz = zz.z - cz;
                float d2 = dx*dx + dy*dy + dz*dz;
                float nd = fminf(dist[4*k+2], d2); dist[4*k+2] = nd;
                if (nd > bestv) { bestv = nd; besti = pbase + 2; }
            }
            {
                float dx = xx.w - cx, dy = yy.w - cy, dz = zz.w - cz;
                float d2 = dx*dx + dy*dy + dz*dz;
                float nd = fminf(dist[4*k+3], d2); dist[4*k+3] = nd;
                if (nd > bestv) { bestv = nd; besti = pbase + 3; }
            }
        }
        // warp argmax reduce, lowest-index tie break (matches jnp.argmax)
#pragma unroll
        for (int off = 16; off > 0; off >>= 1) {
            float ov = __shfl_down_sync(0xffffffffu, bestv, off);
            int   oi = __shfl_down_sync(0xffffffffu, besti, off);
            if (ov > bestv || (ov == bestv && oi < besti)) { bestv = ov; besti = oi; }
        }
        if (lane == 0) { s_rv[wid] = bestv; s_ri[wid] = besti; }
        __syncthreads();
        if (wid == 0) {
            float v = (lane < 16) ? s_rv[lane] : -1.0f;
            int   i = (lane < 16) ? s_ri[lane] : 0x7fffffff;
#pragma unroll
            for (int off = 8; off > 0; off >>= 1) {
                float ov = __shfl_down_sync(0xffffffffu, v, off);
                int   oi = __shfl_down_sync(0xffffffffu, i, off);
                if (ov > v || (ov == v && oi < i)) { v = ov; i = oi; }
            }
            if (lane == 0) {
                s_far  = i;
                s_c[0] = g_sox[b * NPTS + i];
                s_c[1] = g_soy[b * NPTS + i];
                s_c[2] = g_soz[b * NPTS + i];
            }
        }
        __syncthreads();
    }
}

// ---------------- K3: ball query + gather + maxpool ----------------
// CTA per (b, s). warp0: ball query (first-NS-in-order, padded) + diff_coor mean.
// Then 256 threads: per-channel gather + max, write out1 (= sample_x + diff_x = global_x).
__global__ void bq_kernel(const float* __restrict__ x, float* __restrict__ out1) {
    const int s  = blockIdx.x;
    const int b  = blockIdx.y;
    const int bs = b * SPTS + s;
    const int tid  = threadIdx.x;
    const int lane = tid & 31;
    const int wid  = tid >> 5;

    __shared__ int s_nidx[NS];

    if (wid == 0) {
        const int base = b * NPTS;
        float cx = g_scoor[bs*3+0], cy = g_scoor[bs*3+1], cz = g_scoor[bs*3+2];
        int cnt = 0;
        int nbr[NS];
        for (int jb = 0; jb < NPTS && cnt < NS; jb += 32) {
            int j = jb + lane;
            float dx = g_sox[base+j] - cx;
            float dy = g_soy[base+j] - cy;
            float dz = g_soz[base+j] - cz;
            float d2 = dx*dx + dy*dy + dz*dz;
            unsigned m = __ballot_sync(0xffffffffu, d2 < R2);
            while (m && cnt < NS) {
                int bit = __ffs(m) - 1;
                nbr[cnt++] = jb + bit;
                m &= m - 1;
            }
        }
        if (cnt == 0) { nbr[0] = 0; cnt = 1; }
        for (; cnt < NS; cnt++) nbr[cnt] = nbr[0];
        if (lane < NS) s_nidx[lane] = nbr[lane];
        __syncwarp();
        if (lane < NS) {
            int nj = s_nidx[lane];
            float ax = g_sox[base+nj] - cx;
            float ay = g_soy[base+nj] - cy;
            float az = g_soz[base+nj] - cz;
#pragma unroll
            for (int off = 4; off > 0; off >>= 1) {
                ax += __shfl_down_sync(0xffu, ax, off);
                ay += __shfl_down_sync(0xffu, ay, off);
                az += __shfl_down_sync(0xffu, az, off);
            }
            if (lane == 0) {
                g_dcoor[bs*3+0] = ax * 0.125f;
                g_dcoor[bs*3+1] = ay * 0.125f;
                g_dcoor[bs*3+2] = az * 0.125f;
            }
        }
    }
    __syncthreads();

    const int c = tid;                               // channel 0..255
    const float* xb = x + (size_t)b * NPTS * DIM;
    int fidx = g_fps[bs];
    float sx = xb[fidx * DIM + c];
    float m = -3.402823466e38f;
#pragma unroll
    for (int t = 0; t < NS; t++)
        m = fmaxf(m, xb[s_nidx[t] * DIM + c]);
    out1[bs * DIM + c]   = m;        // sample_x + diff_x == global_x
    g_diffx[bs * DIM + c] = m - sx;
    g_sampx[bs * DIM + c] = sx;
}

// ---------------- K4: layernorm (both q-path and k-path) ----------------
__global__ void ln_kernel(const float* __restrict__ gq, const float* __restrict__ bq,
                          const float* __restrict__ gk, const float* __restrict__ bk) {
    const int gw   = blockIdx.x * (blockDim.x >> 5) + (threadIdx.x >> 5);
    const int lane = threadIdx.x & 31;
    for (int rr = 0; rr < 4; rr++) {
        int r = gw * 4 + rr;                    // 0..1023
        const float *src, *g, *bb; float* dst; int row;
        if (r < BATCH*SPTS) { src = g_diffx; g = gq; bb = bq; dst = g_lnq; row = r; }
        else                { src = g_sampx; g = gk; bb = bk; dst = g_lnk; row = r - BATCH*SPTS; }
        const float4* s4 = (const float4*)(src + row * DIM);
        float4 v0 = s4[lane*2], v1 = s4[lane*2+1];
        float sum = v0.x+v0.y+v0.z+v0.w + v1.x+v1.y+v1.z+v1.w;
#pragma unroll
        for (int off = 16; off > 0; off >>= 1) sum += __shfl_xor_sync(0xffffffffu, sum, off);
        float mean = sum * (1.0f/256.0f);
        float d, vsum = 0.0f;
        d = v0.x-mean; vsum += d*d; d = v0.y-mean; vsum += d*d;
        d = v0.z-mean; vsum += d*d; d = v0.w-mean; vsum += d*d;
        d = v1.x-mean; vsum += d*d; d = v1.y-mean; vsum += d*d;
        d = v1.z-mean; vsum += d*d; d = v1.w-mean; vsum += d*d;
#pragma unroll
        for (int off = 16; off > 0; off >>= 1) vsum += __shfl_xor_sync(0xffffffffu, vsum, off);
        float inv = rsqrtf(vsum * (1.0f/256.0f) + 1e-5f);
        const float4* g4 = (const float4*)g;
        const float4* b4 = (const float4*)bb;
        float4 G0 = g4[lane*2], G1 = g4[lane*2+1];
        float4 B0 = b4[lane*2], B1 = b4[lane*2+1];
        float4 o0, o1;
        o0.x = (v0.x-mean)*inv*G0.x + B0.x;  o0.y = (v0.y-mean)*inv*G0.y + B0.y;
        o0.z = (v0.z-mean)*inv*G0.z + B0.z;  o0.w = (v0.w-mean)*inv*G0.w + B0.w;
        o1.x = (v1.x-mean)*inv*G1.x + B1.x;  o1.y = (v1.y-mean)*inv*G1.y + B1.y;
        o1.z = (v1.z-mean)*inv*G1.z + B1.z;  o1.w = (v1.w-mean)*inv*G1.w + B1.w;
        float4* d4 = (float4*)(dst + row * DIM);
        d4[lane*2]   = o0;
        d4[lane*2+1] = o1;
    }
}

// ---------------- K5: q/k projection GEMMs ----------------
// CTA = (rowblock of 8, batch, mat). thread t = output column o.
__global__ void gemm_kernel(const float* __restrict__ Wq, const float* __restrict__ Wk) {
    const int rb = blockIdx.x, b = blockIdx.y, mat = blockIdx.z;
    const float* src = mat ? g_lnk : g_lnq;
    const float* W   = mat ? Wk    : Wq;
    float*       dst = mat ? g_k   : g_q;

    __shared__ float As[8 * DIM];
    const int t = threadIdx.x;                       // 0..255
    const int rowbase = b * SPTS + rb * 8;
#pragma unroll
    for (int i = 0; i < 8; i++)
        As[t + 256*i] = src[rowbase * DIM + t + 256*i];
    __syncthreads();

    const float4* W4 = (const float4*)(W + t * DIM);
    const float4* A4 = (const float4*)As;
    float acc[8] = {0,0,0,0,0,0,0,0};
#pragma unroll 8
    for (int c4 = 0; c4 < 64; c4++) {
        float4 w = W4[c4];
#pragma unroll
        for (int r = 0; r < 8; r++) {
            float4 a = A4[r*64 + c4];
            acc[r] += a.x*w.x + a.y*w.y + a.z*w.z + a.w*w.w;
        }
    }
#pragma unroll
    for (int r = 0; r < 8; r++)
        dst[(rowbase + r) * DIM + t] = acc[r];
}

// ---------------- K6: attention + output2 ----------------
// CTA = (rowblock of 8, batch): scores 8x64, softmax, @ v (torch-view reinterpreted)
__global__ void attn_kernel(float* __restrict__ out2) {
    const int rb = blockIdx.x, b = blockIdx.y;
    __shared__ float As[8 * DIM];       // q rows
    __shared__ float s_att[8 * 64];
    __shared__ float vs[192];
    const int t = threadIdx.x;
    const int rowbase = b * SPTS + rb * 8;
#pragma unroll
    for (int i = 0; i < 8; i++)
        As[t + 256*i] = g_q[rowbase * DIM + t + 256*i];
    if (t < 192)  // v[b,i,j] = diff_coor[b,(3i+j)%64,(3i+j)/64]
        vs[t] = g_dcoor[(b * SPTS + (t & 63)) * 3 + (t >> 6)];
    __syncthreads();

    const int j  = t & 63;
    const int rg = t >> 6;              // 0..3 -> rows rg*2, rg*2+1
    const int r0 = rg * 2, r1 = rg * 2 + 1;
    const float4* K4 = (const float4*)(g_k + (b * SPTS + j) * DIM);
    const float4* A4 = (const float4*)As;
    float a0 = 0.0f, a1 = 0.0f;
#pragma unroll 8
    for (int c4 = 0; c4 < 64; c4++) {
        float4 kk = K4[c4];
        float4 qa = A4[r0*64 + c4];
        float4 qb = A4[r1*64 + c4];
        a0 += qa.x*kk.x + qa.y*kk.y + qa.z*kk.z + qa.w*kk.w;
        a1 += qb.x*kk.x + qb.y*kk.y + qb.z*kk.z + qb.w*kk.w;
    }
    s_att[r0*64 + j] = a0 * 0.0625f;    // scale = 1/sqrt(256)
    s_att[r1*64 + j] = a1 * 0.0625f;
    __syncthreads();

    const int wid = t >> 5, lane = t & 31;   // warp per row (8 rows)
    float x0 = s_att[wid*64 + lane];
    float x1 = s_att[wid*64 + lane + 32];
    float mx = fmaxf(x0, x1);
#pragma unroll
    for (int off = 16; off > 0; off >>= 1) mx = fmaxf(mx, __shfl_xor_sync(0xffffffffu, mx, off));
    float e0 = expf(x0 - mx), e1 = expf(x1 - mx);
    float ssum = e0 + e1;
#pragma unroll
    for (int off = 16; off > 0; off >>= 1) ssum += __shfl_xor_sync(0xffffffffu, ssum, off);
    float rinv = 1.0f / ssum;
    float p0 = e0 * rinv, p1 = e1 * rinv;
    float c0 = p0 * vs[lane*3+0] + p1 * vs[(lane+32)*3+0];
    float c1 = p0 * vs[lane*3+1] + p1 * vs[(lane+32)*3+1];
    float c2 = p0 * vs[lane*3+2] + p1 * vs[(lane+32)*3+2];
#pragma unroll
    for (int off = 16; off > 0; off >>= 1) {
        c0 += __shfl_xor_sync(0xffffffffu, c0, off);
        c1 += __shfl_xor_sync(0xffffffffu, c1, off);
        c2 += __shfl_xor_sync(0xffffffffu, c2, off);
    }
    if (lane == 0) {
        int row = rowbase + wid;
        out2[row*3+0] = g_scoor[row*3+0] + c0;
        out2[row*3+1] = g_scoor[row*3+1] + c1;
        out2[row*3+2] = g_scoor[row*3+2] + c2;
    }
}

// ---------------- launcher ----------------
extern "C" void kernel_launch(void* const* d_in, const int* in_sizes, int n_in,
                              void* d_out, int out_size) {
    const float* x    = (const float*)d_in[0];
    const float* coor = (const float*)d_in[1];
    const float* Wq   = (const float*)d_in[2];
    const float* Wk   = (const float*)d_in[3];
    const float* lnqg = (const float*)d_in[4];
    const float* lnqb = (const float*)d_in[5];
    const float* lnkg = (const float*)d_in[6];
    const float* lnkb = (const float*)d_in[7];

    float* out1 = (float*)d_out;                       // [8,64,256]
    float* out2 = out1 + BATCH * SPTS * DIM;           // [8,64,3]

    pack_kernel<<<256, 1024>>>(coor);
    fps_kernel<<<8, 512>>>();
    bq_kernel<<<dim3(SPTS, BATCH), 256>>>(x, out1);
    ln_kernel<<<32, 256>>>(lnqg, lnqb, lnkg, lnkb);
    gemm_kernel<<<dim3(8, BATCH, 2), 256>>>(Wq, Wk);
    attn_kernel<<<dim3(8, BATCH), 256>>>(out2);
}

// round 2
// speedup vs baseline: 2.3015x; 2.3015x over previous
#include <cuda_runtime.h>
#include <cstdint>

#define BATCH 8
#define NPTS  32768
#define DIM   256
#define SPTS  64
#define NS    8
#define R2    16.0f
#define FCTAS 8                 // CTAs per batch (cluster size)
#define SEG   (NPTS/FCTAS)      // 4096 points per CTA
#define FPT   (SEG/512)         // 8 points per thread

// ---------------- scratch (no allocations allowed) ----------------
__device__ int   g_fps[BATCH*SPTS];
__device__ float g_scoor[BATCH*SPTS*3];
__device__ float g_dcoor[BATCH*SPTS*3];
__device__ float g_diffx[BATCH*SPTS*DIM];
__device__ float g_sampx[BATCH*SPTS*DIM];
__device__ float g_q[BATCH*SPTS*DIM];
__device__ float g_k[BATCH*SPTS*DIM];

__device__ __forceinline__ uint32_t smem_u32(const void* p) {
    uint32_t a;
    asm("{ .reg .u64 t; cvta.to.shared.u64 t, %1; cvt.u32.u64 %0, t; }" : "=r"(a) : "l"(p));
    return a;
}
__device__ __forceinline__ uint32_t mapa_rank(uint32_t a, uint32_t r) {
    uint32_t o;
    asm("mapa.shared::cluster.u32 %0, %1, %2;" : "=r"(o) : "r"(a), "r"(r));
    return o;
}
__device__ __forceinline__ void st_cluster_f32(uint32_t a, float v) {
    asm volatile("st.shared::cluster.f32 [%0], %1;" :: "r"(a), "f"(v) : "memory");
}
__device__ __forceinline__ void st_cluster_s32(uint32_t a, int v) {
    asm volatile("st.shared::cluster.u32 [%0], %1;" :: "r"(a), "r"(v) : "memory");
}
#define CLUSTER_SYNC() do { \
    asm volatile("barrier.cluster.arrive.aligned;" ::: "memory"); \
    asm volatile("barrier.cluster.wait.aligned;" ::: "memory"); \
} while (0)

// ---------------- K1: farthest point sampling ----------------
// 8-CTA cluster per batch. Coordinates register-resident (8 pts/thread).
// Per iteration: per-thread update+argmax -> warp reduce -> CTA reduce ->
// DSMEM candidate broadcast (double buffered) -> cluster.sync -> local pick.
__global__ void __cluster_dims__(FCTAS, 1, 1) __launch_bounds__(512, 1)
fps_kernel(const float* __restrict__ coor) {
    const int b   = blockIdx.x / FCTAS;
    const int r   = blockIdx.x % FCTAS;
    const int tid = threadIdx.x;
    const int lane = tid & 31;
    const int wid  = tid >> 5;

    __shared__ float s_v[16], s_x[16], s_y[16], s_z[16];
    __shared__ int   s_i[16];
    __shared__ float c_v[2][FCTAS], c_x[2][FCTAS], c_y[2][FCTAS], c_z[2][FCTAS];
    __shared__ int   c_i[2][FCTAS];

    const int gbase = r * SEG + tid * FPT;      // index within batch
    const float* cp = coor + ((size_t)b * NPTS + gbase) * 3;

    float fl[24];
    {
        const float4* c4 = (const float4*)cp;   // 96B per thread, 16B aligned
#pragma unroll
        for (int i = 0; i < 6; i++) {
            float4 v = c4[i];
            fl[4*i+0] = v.x; fl[4*i+1] = v.y; fl[4*i+2] = v.z; fl[4*i+3] = v.w;
        }
    }
    float px[FPT], py[FPT], pz[FPT], dist[FPT];
#pragma unroll
    for (int i = 0; i < FPT; i++) {
        px[i] = fl[3*i]; py[i] = fl[3*i+1]; pz[i] = fl[3*i+2];
        dist[i] = 1e10f;
    }

    float cx = coor[(size_t)b*NPTS*3 + 0];
    float cy = coor[(size_t)b*NPTS*3 + 1];
    float cz = coor[(size_t)b*NPTS*3 + 2];
    int far = 0;

    for (int it = 0; it < SPTS; it++) {
        if (r == 0 && tid == 0) {
            g_fps[b*SPTS + it] = far;
            g_scoor[(b*SPTS + it)*3 + 0] = cx;
            g_scoor[(b*SPTS + it)*3 + 1] = cy;
            g_scoor[(b*SPTS + it)*3 + 2] = cz;
        }
        if (it == SPTS - 1) break;

        float bv = -1.0f, bx = 0.f, by = 0.f, bz = 0.f;
        int   bi = 0;
#pragma unroll
        for (int i = 0; i < FPT; i++) {
            float dx = px[i] - cx, dy = py[i] - cy, dz = pz[i] - cz;
            float d2 = dx*dx + dy*dy + dz*dz;
            float nd = fminf(dist[i], d2);
            dist[i] = nd;
            if (nd > bv) { bv = nd; bi = gbase + i; bx = px[i]; by = py[i]; bz = pz[i]; }
        }
        // warp argmax (strict >, lowest index tie-break; ascending order preserved)
#pragma unroll
        for (int off = 16; off > 0; off >>= 1) {
            float ov = __shfl_down_sync(~0u, bv, off);
            int   oi = __shfl_down_sync(~0u, bi, off);
            float ox = __shfl_down_sync(~0u, bx, off);
            float oy = __shfl_down_sync(~0u, by, off);
            float oz = __shfl_down_sync(~0u, bz, off);
            if (ov > bv || (ov == bv && oi < bi)) { bv = ov; bi = oi; bx = ox; by = oy; bz = oz; }
        }
        if (lane == 0) { s_v[wid] = bv; s_i[wid] = bi; s_x[wid] = bx; s_y[wid] = by; s_z[wid] = bz; }
        __syncthreads();

        const int p = it & 1;
        if (wid == 0) {
            float v = (lane < 16) ? s_v[lane] : -1.0f;
            int   i = (lane < 16) ? s_i[lane] : 0x7fffffff;
            float xx = (lane < 16) ? s_x[lane] : 0.f;
            float yy = (lane < 16) ? s_y[lane] : 0.f;
            float zz = (lane < 16) ? s_z[lane] : 0.f;
#pragma unroll
            for (int off = 8; off > 0; off >>= 1) {
                float ov = __shfl_down_sync(~0u, v, off);
                int   oi = __shfl_down_sync(~0u, i, off);
                float ox = __shfl_down_sync(~0u, xx, off);
                float oy = __shfl_down_sync(~0u, yy, off);
                float oz = __shfl_down_sync(~0u, zz, off);
                if (ov > v || (ov == v && oi < i)) { v = ov; i = oi; xx = ox; yy = oy; zz = oz; }
            }
            // broadcast CTA winner to lanes 0..7, each lane ships to one peer CTA
            v  = __shfl_sync(~0u, v, 0);
            i  = __shfl_sync(~0u, i, 0);
            xx = __shfl_sync(~0u, xx, 0);
            yy = __shfl_sync(~0u, yy, 0);
            zz = __shfl_sync(~0u, zz, 0);
            if (lane < FCTAS) {
                st_cluster_f32(mapa_rank(smem_u32(&c_v[p][r]), lane), v);
                st_cluster_s32(mapa_rank(smem_u32(&c_i[p][r]), lane), i);
                st_cluster_f32(mapa_rank(smem_u32(&c_x[p][r]), lane), xx);
                st_cluster_f32(mapa_rank(smem_u32(&c_y[p][r]), lane), yy);
                st_cluster_f32(mapa_rank(smem_u32(&c_z[p][r]), lane), zz);
            }
        }
        CLUSTER_SYNC();   // release/acquire: remote stores visible after this

        float bbv = -1.0f; int bbi = 0x7fffffff;
#pragma unroll
        for (int rr = 0; rr < FCTAS; rr++) {      // ascending rank = ascending index
            float v = c_v[p][rr]; int i = c_i[p][rr];
            if (v > bbv || (v == bbv && i < bbi)) {
                bbv = v; bbi = i;
                cx = c_x[p][rr]; cy = c_y[p][rr]; cz = c_z[p][rr];
            }
        }
        far = bbi;
    }
}

// ---------------- K2: ball query + gather + maxpool ----------------
// CTA per (b,s). 8 warps scan disjoint 4096-pt segments (first-NS per segment,
// prefetched); thread0 merges in segment order = global first-NS semantics.
__global__ void __launch_bounds__(256) bq_kernel(const float* __restrict__ x,
                                                 const float* __restrict__ coor,
                                                 float* __restrict__ out1) {
    const int s  = blockIdx.x;
    const int b  = blockIdx.y;
    const int bs = b * SPTS + s;
    const int tid  = threadIdx.x;
    const int lane = tid & 31;
    const int w    = tid >> 5;

    __shared__ int s_hits[8][NS];
    __shared__ int s_cnt[8];
    __shared__ int s_nidx[NS];

    const float cx = g_scoor[bs*3+0], cy = g_scoor[bs*3+1], cz = g_scoor[bs*3+2];
    const float* cb = coor + (size_t)b * NPTS * 3;

    {
        const int segb = w * 4096;
        int cnt = 0;
        int nbr[NS];
        int j = segb + lane;
        float qx = cb[j*3], qy = cb[j*3+1], qz = cb[j*3+2];   // prefetch
        for (int jb = 0; jb < 4096 && cnt < NS; jb += 32) {
            float ax = qx, ay = qy, az = qz;
            int jn = segb + ((jb + 32 < 4096) ? jb + 32 : jb) + lane;
            qx = cb[jn*3]; qy = cb[jn*3+1]; qz = cb[jn*3+2];
            float dx = ax - cx, dy = ay - cy, dz = az - cz;
            float d2 = dx*dx + dy*dy + dz*dz;
            unsigned m = __ballot_sync(~0u, d2 < R2);
            while (m && cnt < NS) {
                int bit = __ffs(m) - 1;
                nbr[cnt++] = segb + jb + bit;
                m &= m - 1;
            }
        }
        if (lane == 0) {
            s_cnt[w] = cnt;
#pragma unroll
            for (int i = 0; i < NS; i++)
                if (i < cnt) s_hits[w][i] = nbr[i];
        }
    }
    __syncthreads();

    if (tid == 0) {
        int tot = 0;
#pragma unroll
        for (int ww = 0; ww < 8; ww++) {
            int c = s_cnt[ww];
#pragma unroll
            for (int i = 0; i < NS; i++)
                if (i < c && tot < NS) { s_nidx[tot] = s_hits[ww][i]; tot++; }
        }
        if (tot == 0) { s_nidx[0] = 0; tot = 1; }
        int f = s_nidx[0];
        for (; tot < NS; tot++) s_nidx[tot] = f;
    }
    __syncthreads();

    if (tid < NS) {                       // diff_coor mean over 8 neighbors
        int nj = s_nidx[tid];
        float ax = cb[nj*3+0] - cx;
        float ay = cb[nj*3+1] - cy;
        float az = cb[nj*3+2] - cz;
#pragma unroll
        for (int off = 4; off > 0; off >>= 1) {
            ax += __shfl_down_sync(0xffu, ax, off);
            ay += __shfl_down_sync(0xffu, ay, off);
            az += __shfl_down_sync(0xffu, az, off);
        }
        if (tid == 0) {
            g_dcoor[bs*3+0] = ax * 0.125f;
            g_dcoor[bs*3+1] = ay * 0.125f;
            g_dcoor[bs*3+2] = az * 0.125f;
        }
    }

    const int c = tid;                                   // channel
    const float* xb = x + (size_t)b * NPTS * DIM;
    int fidx = g_fps[bs];
    float sx = xb[(size_t)fidx * DIM + c];
    float m = -3.402823466e38f;
#pragma unroll
    for (int t = 0; t < NS; t++)
        m = fmaxf(m, xb[(size_t)s_nidx[t] * DIM + c]);
    out1[bs*DIM + c]    = m;             // sample_x + diff_x == global_x
    g_diffx[bs*DIM + c] = m - sx;
    g_sampx[bs*DIM + c] = sx;
}

// ---------------- K3: fused layernorm + q/k projection GEMM ----------------
__global__ void __launch_bounds__(256) gemmln_kernel(
        const float* __restrict__ Wq, const float* __restrict__ Wk,
        const float* __restrict__ gq, const float* __restrict__ bq,
        const float* __restrict__ gk, const float* __restrict__ bk) {
    const int rb = blockIdx.x, b = blockIdx.y, mat = blockIdx.z;
    const float* src = mat ? g_sampx : g_diffx;
    const float* W   = mat ? Wk      : Wq;
    const float* gg  = mat ? gk      : gq;
    const float* bb  = mat ? bk      : bq;
    float*       dst = mat ? g_k     : g_q;

    __shared__ float As[8 * DIM];
    const int t = threadIdx.x;
    const int rowbase = b * SPTS + rb * 8;
#pragma unroll
    for (int i = 0; i < 8; i++)
        As[t + 256*i] = src[rowbase * DIM + t + 256*i];
    __syncthreads();

    {   // layernorm: warp w normalizes row w in place
        const int w = t >> 5, lane = t & 31;
        float4* r4 = (float4*)(As + w * DIM);
        float4 v0 = r4[lane*2], v1 = r4[lane*2+1];
        float sum = v0.x+v0.y+v0.z+v0.w + v1.x+v1.y+v1.z+v1.w;
        float sq  = v0.x*v0.x+v0.y*v0.y+v0.z*v0.z+v0.w*v0.w
                  + v1.x*v1.x+v1.y*v1.y+v1.z*v1.z+v1.w*v1.w;
#pragma unroll
        for (int off = 16; off > 0; off >>= 1) {
            sum += __shfl_xor_sync(~0u, sum, off);
            sq  += __shfl_xor_sync(~0u, sq,  off);
        }
        float mean = sum * (1.0f/256.0f);
        float var  = sq * (1.0f/256.0f) - mean * mean;
        float inv  = rsqrtf(var + 1e-5f);
        const float4* g4 = (const float4*)gg;
        const float4* b4 = (const float4*)bb;
        float4 G0 = g4[lane*2], G1 = g4[lane*2+1];
        float4 B0 = b4[lane*2], B1 = b4[lane*2+1];
        v0.x = (v0.x-mean)*inv*G0.x + B0.x;  v0.y = (v0.y-mean)*inv*G0.y + B0.y;
        v0.z = (v0.z-mean)*inv*G0.z + B0.z;  v0.w = (v0.w-mean)*inv*G0.w + B0.w;
        v1.x = (v1.x-mean)*inv*G1.x + B1.x;  v1.y = (v1.y-mean)*inv*G1.y + B1.y;
        v1.z = (v1.z-mean)*inv*G1.z + B1.z;  v1.w = (v1.w-mean)*inv*G1.w + B1.w;
        r4[lane*2]   = v0;
        r4[lane*2+1] = v1;
    }
    __syncthreads();

    const float4* W4 = (const float4*)(W + t * DIM);
    const float4* A4 = (const float4*)As;
    float acc[8] = {0,0,0,0,0,0,0,0};
#pragma unroll 8
    for (int c4 = 0; c4 < 64; c4++) {
        float4 w = W4[c4];
#pragma unroll
        for (int r = 0; r < 8; r++) {
            float4 a = A4[r*64 + c4];
            acc[r] += a.x*w.x + a.y*w.y + a.z*w.z + a.w*w.w;
        }
    }
#pragma unroll
    for (int r = 0; r < 8; r++)
        dst[(rowbase + r) * DIM + t] = acc[r];
}

// ---------------- K4: attention + output2 ----------------
__global__ void __launch_bounds__(256) attn_kernel(float* __restrict__ out2) {
    const int rb = blockIdx.x, b = blockIdx.y;
    __shared__ float As[8 * DIM];
    __shared__ float s_att[8 * 64];
    __shared__ float vs[192];
    const int t = threadIdx.x;
    const int rowbase = b * SPTS + rb * 8;
#pragma unroll
    for (int i = 0; i < 8; i++)
        As[t + 256*i] = g_q[rowbase * DIM + t + 256*i];
    if (t < 192)   // v[b,i,j] = diff_coor[b,(3i+j)%64,(3i+j)/64] (torch view reinterp)
        vs[t] = g_dcoor[(b * SPTS + (t & 63)) * 3 + (t >> 6)];
    __syncthreads();

    const int j  = t & 63;
    const int rg = t >> 6;
    const int r0 = rg * 2, r1 = rg * 2 + 1;
    const float4* K4 = (const float4*)(g_k + (b * SPTS + j) * DIM);
    const float4* A4 = (const float4*)As;
    float a0 = 0.0f, a1 = 0.0f;
#pragma unroll 8
    for (int c4 = 0; c4 < 64; c4++) {
        float4 kk = K4[c4];
        float4 qa = A4[r0*64 + c4];
        float4 qb = A4[r1*64 + c4];
        a0 += qa.x*kk.x + qa.y*kk.y + qa.z*kk.z + qa.w*kk.w;
        a1 += qb.x*kk.x + qb.y*kk.y + qb.z*kk.z + qb.w*kk.w;
    }
    s_att[r0*64 + j] = a0 * 0.0625f;
    s_att[r1*64 + j] = a1 * 0.0625f;
    __syncthreads();

    const int wid = t >> 5, lane = t & 31;
    float x0 = s_att[wid*64 + lane];
    float x1 = s_att[wid*64 + lane + 32];
    float mx = fmaxf(x0, x1);
#pragma unroll
    for (int off = 16; off > 0; off >>= 1) mx = fmaxf(mx, __shfl_xor_sync(~0u, mx, off));
    float e0 = expf(x0 - mx), e1 = expf(x1 - mx);
    float ssum = e0 + e1;
#pragma unroll
    for (int off = 16; off > 0; off >>= 1) ssum += __shfl_xor_sync(~0u, ssum, off);
    float rinv = 1.0f / ssum;
    float p0 = e0 * rinv, p1 = e1 * rinv;
    float c0 = p0 * vs[lane*3+0] + p1 * vs[(lane+32)*3+0];
    float c1 = p0 * vs[lane*3+1] + p1 * vs[(lane+32)*3+1];
    float c2 = p0 * vs[lane*3+2] + p1 * vs[(lane+32)*3+2];
#pragma unroll
    for (int off = 16; off > 0; off >>= 1) {
        c0 += __shfl_xor_sync(~0u, c0, off);
        c1 += __shfl_xor_sync(~0u, c1, off);
        c2 += __shfl_xor_sync(~0u, c2, off);
    }
    if (lane == 0) {
        int row = rowbase + wid;
        out2[row*3+0] = g_scoor[row*3+0] + c0;
        out2[row*3+1] = g_scoor[row*3+1] + c1;
        out2[row*3+2] = g_scoor[row*3+2] + c2;
    }
}

// ---------------- launcher ----------------
extern "C" void kernel_launch(void* const* d_in, const int* in_sizes, int n_in,
                              void* d_out, int out_size) {
    const float* x    = (const float*)d_in[0];
    const float* coor = (const float*)d_in[1];
    const float* Wq   = (const float*)d_in[2];
    const float* Wk   = (const float*)d_in[3];
    const float* lnqg = (const float*)d_in[4];
    const float* lnqb = (const float*)d_in[5];
    const float* lnkg = (const float*)d_in[6];
    const float* lnkb = (const float*)d_in[7];

    float* out1 = (float*)d_out;                 // [8,64,256]
    float* out2 = out1 + BATCH * SPTS * DIM;     // [8,64,3]

    fps_kernel<<<BATCH * FCTAS, 512>>>(coor);
    bq_kernel<<<dim3(SPTS, BATCH), 256>>>(x, coor, out1);
    gemmln_kernel<<<dim3(8, BATCH, 2), 256>>>(Wq, Wk, lnqg, lnqb, lnkg, lnkb);
    attn_kernel<<<dim3(8, BATCH), 256>>>(out2);
}